// round 1
// baseline (speedup 1.0000x reference)
#include <cuda_runtime.h>
#include <cuda_bf16.h>

// Problem constants
#define BB 4
#define SS 2048
#define DD 1024
#define HH 16
#define HDIM 64

// Intermediate buffers (static device globals: allowed; no runtime alloc)
__device__ float g_q[BB * SS * DD];
__device__ float g_k[BB * SS * DD];
__device__ float g_v[BB * SS * DD];
__device__ float g_ctx[BB * SS * DD];

// ---------------------------------------------------------------------------
// SGEMM: C[M,N] = A[M,K] @ B[K,N] (+ bias[N] if BIAS)
// Block tile 128x128, K-step 8, 256 threads, 8x8 per thread (split fragments).
// ---------------------------------------------------------------------------
template <bool BIAS>
__global__ __launch_bounds__(256)
void sgemm_128x128(const float* __restrict__ A, const float* __restrict__ B,
                   const float* __restrict__ bias, float* __restrict__ C,
                   int M, int N, int K) {
    __shared__ float As[8][128];   // transposed A tile: As[k][m]
    __shared__ float Bs[8][128];   // Bs[k][n]

    const int tid = threadIdx.x;
    const int tx = tid & 15;       // 0..15 (N fragment)
    const int ty = tid >> 4;       // 0..15 (M fragment)
    const int m0 = blockIdx.y * 128;
    const int n0 = blockIdx.x * 128;

    // A load: 128 rows x 8 cols = 256 float4 (one per thread)
    const int la_row = tid >> 1;          // 0..127
    const int la_col = (tid & 1) * 4;     // 0 or 4
    // B load: 8 rows x 128 cols = 256 float4
    const int lb_row = tid >> 5;          // 0..7
    const int lb_col = (tid & 31) * 4;    // 0..124

    const float* Ap = A + (size_t)(m0 + la_row) * K + la_col;
    const float* Bp = B + (size_t)lb_row * N + n0 + lb_col;

    float acc[8][8];
#pragma unroll
    for (int i = 0; i < 8; i++)
#pragma unroll
        for (int j = 0; j < 8; j++) acc[i][j] = 0.f;

    float4 pa = *(const float4*)Ap;
    float4 pb = *(const float4*)Bp;

    const int ntiles = K >> 3;
    for (int t = 0; t < ntiles; t++) {
        As[la_col + 0][la_row] = pa.x;
        As[la_col + 1][la_row] = pa.y;
        As[la_col + 2][la_row] = pa.z;
        As[la_col + 3][la_row] = pa.w;
        *(float4*)&Bs[lb_row][lb_col] = pb;
        __syncthreads();

        if (t + 1 < ntiles) {
            pa = *(const float4*)(Ap + (t + 1) * 8);
            pb = *(const float4*)(Bp + (size_t)(t + 1) * 8 * N);
        }

#pragma unroll
        for (int kk = 0; kk < 8; kk++) {
            float ra[8], rb[8];
            *(float4*)&ra[0] = *(float4*)&As[kk][ty * 4];
            *(float4*)&ra[4] = *(float4*)&As[kk][64 + ty * 4];
            *(float4*)&rb[0] = *(float4*)&Bs[kk][tx * 4];
            *(float4*)&rb[4] = *(float4*)&Bs[kk][64 + tx * 4];
#pragma unroll
            for (int i = 0; i < 8; i++)
#pragma unroll
                for (int j = 0; j < 8; j++) acc[i][j] += ra[i] * rb[j];
        }
        __syncthreads();
    }

    // Epilogue: 4 regions of 4x4, float4 stores
#pragma unroll
    for (int hi = 0; hi < 2; hi++) {
#pragma unroll
        for (int i = 0; i < 4; i++) {
            const int row = m0 + hi * 64 + ty * 4 + i;
#pragma unroll
            for (int hj = 0; hj < 2; hj++) {
                const int col = n0 + hj * 64 + tx * 4;
                float4 v;
                v.x = acc[hi * 4 + i][hj * 4 + 0];
                v.y = acc[hi * 4 + i][hj * 4 + 1];
                v.z = acc[hi * 4 + i][hj * 4 + 2];
                v.w = acc[hi * 4 + i][hj * 4 + 3];
                if (BIAS) {
                    v.x += bias[col + 0];
                    v.y += bias[col + 1];
                    v.z += bias[col + 2];
                    v.w += bias[col + 3];
                }
                *(float4*)&C[(size_t)row * N + col] = v;
            }
        }
    }
}

// ---------------------------------------------------------------------------
// Flash-attention (fp32), 64x64 tiles, head_dim=64, online softmax.
// Causal mask with +1 lookahead: key k allowed iff k <= q + 1.
// smem: Qs[64][64] + Kbuf[64][64] (rotation-swizzled K, reused for P) +
//       Vs[64][64] = 48 KB static.
// ---------------------------------------------------------------------------
__global__ __launch_bounds__(256)
void attn_kernel(const float* __restrict__ Qg, const float* __restrict__ Kg,
                 const float* __restrict__ Vg, float* __restrict__ Ctx) {
    __shared__ float Qs[64 * 64];
    __shared__ float Kbuf[64 * 64];   // K rotated; later reused as P (plain)
    __shared__ float Vs[64 * 64];

    const int q0 = blockIdx.x * 64;
    const int h = blockIdx.y;
    const int b = blockIdx.z;
    const int tid = threadIdx.x;
    const int tx = tid & 15;
    const int ty = tid >> 4;
    const int lrow = tid >> 4;          // load row 0..15 (step 16)
    const int lcol = (tid & 15) * 4;    // load col 0,4,...,60

    const size_t head_off = ((size_t)b * SS) * DD + (size_t)h * HDIM;
    const float* qbase = Qg + head_off + (size_t)q0 * DD;
    const float* kbase = Kg + head_off;
    const float* vbase = Vg + head_off;

    // Load Q tile (plain layout, broadcast reads later)
#pragma unroll
    for (int r = 0; r < 64; r += 16) {
        *(float4*)&Qs[(r + lrow) * 64 + lcol] =
            *(const float4*)&qbase[(size_t)(r + lrow) * DD + lcol];
    }

    float o[4][4];
    float m_i[4], l_i[4];
#pragma unroll
    for (int i = 0; i < 4; i++) {
        m_i[i] = -1e30f;
        l_i[i] = 0.f;
#pragma unroll
        for (int j = 0; j < 4; j++) o[i][j] = 0.f;
    }

    const int ktiles = min(q0 / 64 + 2, SS / 64);

    __syncthreads();

    for (int t = 0; t < ktiles; t++) {
        const int k0 = t * 64;
        const float* kb = kbase + (size_t)k0 * DD;
        const float* vb = vbase + (size_t)k0 * DD;

        // Load K (rotation swizzle: element (row, d) -> Kbuf[row*64 + ((d+row)&63)])
        // and V (plain).
#pragma unroll
        for (int r = 0; r < 64; r += 16) {
            const int krow = r + lrow;
            float4 kv = *(const float4*)&kb[(size_t)krow * DD + lcol];
            Kbuf[krow * 64 + ((lcol + 0 + krow) & 63)] = kv.x;
            Kbuf[krow * 64 + ((lcol + 1 + krow) & 63)] = kv.y;
            Kbuf[krow * 64 + ((lcol + 2 + krow) & 63)] = kv.z;
            Kbuf[krow * 64 + ((lcol + 3 + krow) & 63)] = kv.w;
            *(float4*)&Vs[krow * 64 + lcol] =
                *(const float4*)&vb[(size_t)krow * DD + lcol];
        }
        __syncthreads();

        // S = Q K^T  (4x4 fragment per thread)
        float s[4][4];
#pragma unroll
        for (int i = 0; i < 4; i++)
#pragma unroll
            for (int j = 0; j < 4; j++) s[i][j] = 0.f;

#pragma unroll 8
        for (int d = 0; d < 64; d++) {
            float ra[4], rb[4];
#pragma unroll
            for (int i = 0; i < 4; i++) ra[i] = Qs[(ty * 4 + i) * 64 + d];
#pragma unroll
            for (int j = 0; j < 4; j++) {
                const int kr = tx * 4 + j;
                rb[j] = Kbuf[kr * 64 + ((d + kr) & 63)];
            }
#pragma unroll
            for (int i = 0; i < 4; i++)
#pragma unroll
                for (int j = 0; j < 4; j++) s[i][j] += ra[i] * rb[j];
        }

        // Scale + causal mask (k <= q+1 allowed)
        const bool need_mask = (k0 >= q0);
#pragma unroll
        for (int i = 0; i < 4; i++)
#pragma unroll
            for (int j = 0; j < 4; j++) {
                s[i][j] *= 0.125f;  // 1/sqrt(64)
                if (need_mask && (k0 + tx * 4 + j > q0 + ty * 4 + i + 1))
                    s[i][j] = -1e30f;
            }

        // Online softmax: row stats across the 16 tx-lanes of each row group
        float p[4][4];
        float psum[4];
#pragma unroll
        for (int i = 0; i < 4; i++) {
            float tmax = fmaxf(fmaxf(s[i][0], s[i][1]), fmaxf(s[i][2], s[i][3]));
#pragma unroll
            for (int off = 8; off; off >>= 1)
                tmax = fmaxf(tmax, __shfl_xor_sync(0xffffffffu, tmax, off));
            const float mnew = fmaxf(m_i[i], tmax);
            const float corr = __expf(m_i[i] - mnew);
            float ps = 0.f;
#pragma unroll
            for (int j = 0; j < 4; j++) {
                p[i][j] = __expf(s[i][j] - mnew);
                ps += p[i][j];
            }
#pragma unroll
            for (int off = 8; off; off >>= 1)
                ps += __shfl_xor_sync(0xffffffffu, ps, off);
            l_i[i] = l_i[i] * corr + ps;
            m_i[i] = mnew;
#pragma unroll
            for (int j = 0; j < 4; j++) o[i][j] *= corr;
            psum[i] = ps;
            (void)psum;
        }

        __syncthreads();  // all threads done reading Kbuf (as K)

        // Write P into Kbuf (plain layout)
#pragma unroll
        for (int i = 0; i < 4; i++) {
            float4 pv;
            pv.x = p[i][0]; pv.y = p[i][1]; pv.z = p[i][2]; pv.w = p[i][3];
            *(float4*)&Kbuf[(ty * 4 + i) * 64 + tx * 4] = pv;
        }
        __syncthreads();

        // O += P @ V
#pragma unroll 4
        for (int kk = 0; kk < 64; kk++) {
            float4 v = *(float4*)&Vs[kk * 64 + tx * 4];
#pragma unroll
            for (int i = 0; i < 4; i++) {
                const float pv = Kbuf[(ty * 4 + i) * 64 + kk];
                o[i][0] += pv * v.x;
                o[i][1] += pv * v.y;
                o[i][2] += pv * v.z;
                o[i][3] += pv * v.w;
            }
        }
        __syncthreads();  // protect Kbuf/Vs before next tile's loads
    }

    // Epilogue: normalize and write ctx[b][q][h*64 + col]
    float* cbase = Ctx + head_off + (size_t)q0 * DD;
#pragma unroll
    for (int i = 0; i < 4; i++) {
        const float inv_l = 1.0f / l_i[i];
        float4 v;
        v.x = o[i][0] * inv_l;
        v.y = o[i][1] * inv_l;
        v.z = o[i][2] * inv_l;
        v.w = o[i][3] * inv_l;
        *(float4*)&cbase[(size_t)(ty * 4 + i) * DD + tx * 4] = v;
    }
}

// ---------------------------------------------------------------------------
// kernel_launch
// ---------------------------------------------------------------------------
extern "C" void kernel_launch(void* const* d_in, const int* in_sizes, int n_in,
                              void* d_out, int out_size) {
    (void)in_sizes; (void)n_in; (void)out_size;
    const float* x  = (const float*)d_in[0];
    const float* Wq = (const float*)d_in[1];
    const float* Wk = (const float*)d_in[2];
    const float* Wv = (const float*)d_in[3];
    const float* Wo = (const float*)d_in[4];
    const float* bo = (const float*)d_in[5];
    float* out = (float*)d_out;

    float *q, *k, *v, *ctx;
    cudaGetSymbolAddress((void**)&q, g_q);
    cudaGetSymbolAddress((void**)&k, g_k);
    cudaGetSymbolAddress((void**)&v, g_v);
    cudaGetSymbolAddress((void**)&ctx, g_ctx);

    const int M = BB * SS;  // 8192
    dim3 gemm_grid(DD / 128, M / 128);  // (8, 64)

    sgemm_128x128<false><<<gemm_grid, 256>>>(x, Wq, nullptr, q, M, DD, DD);
    sgemm_128x128<false><<<gemm_grid, 256>>>(x, Wk, nullptr, k, M, DD, DD);
    sgemm_128x128<false><<<gemm_grid, 256>>>(x, Wv, nullptr, v, M, DD, DD);

    dim3 attn_grid(SS / 64, HH, BB);  // (32, 16, 4)
    attn_kernel<<<attn_grid, 256>>>(q, k, v, ctx);

    sgemm_128x128<true><<<gemm_grid, 256>>>(ctx, Wo, bo, out, M, DD, DD);
}